// round 1
// baseline (speedup 1.0000x reference)
#include <cuda_runtime.h>
#include <math.h>

#define BB 2
#define SS 2049
#define EE 512
#define HH 8
#define DD 64
#define WINW 1024
#define MROWS (BB * SS)            // 4098
#define SCALE 0.125f               // D^-0.5
#define BIASC (-1.9073486328125e-6f)  // -0.5/(512^2)

// Scratch (device globals: no allocation allowed)
__device__ float g_q[MROWS * EE];
__device__ float g_k[MROWS * EE];
__device__ float g_v[MROWS * EE];
__device__ float g_ao[MROWS * EE];
__device__ float g_gq[MROWS];
__device__ float g_gk[MROWS];

// ---------------------------------------------------------------------------
// SGEMM: C[M,512] = A[M,512] @ B[512,512] + bias[512]
// 128x128 tile, BK=8, 256 threads, 8x8 microtile
// ---------------------------------------------------------------------------
__global__ __launch_bounds__(256) void sgemm_bias_kernel(
    const float* __restrict__ A, const float* __restrict__ B,
    const float* __restrict__ bias, float* __restrict__ C, int M)
{
    __shared__ float As[8][132];
    __shared__ float Bs[8][132];

    const int bx = blockIdx.x, by = blockIdx.y;
    const int tid = threadIdx.x;
    const int ty = tid >> 4, tx = tid & 15;
    const int row0 = by * 128, col0 = bx * 128;

    float acc[8][8];
#pragma unroll
    for (int i = 0; i < 8; i++)
#pragma unroll
        for (int j = 0; j < 8; j++) acc[i][j] = 0.f;

    const int arow = tid >> 1, acol = (tid & 1) * 4;
    const int brow = tid >> 5, bcol = (tid & 31) * 4;

    for (int k0 = 0; k0 < 512; k0 += 8) {
        float4 av = make_float4(0.f, 0.f, 0.f, 0.f);
        if (row0 + arow < M)
            av = *(const float4*)&A[(size_t)(row0 + arow) * 512 + k0 + acol];
        As[acol + 0][arow] = av.x;
        As[acol + 1][arow] = av.y;
        As[acol + 2][arow] = av.z;
        As[acol + 3][arow] = av.w;

        float4 bv = *(const float4*)&B[(size_t)(k0 + brow) * 512 + col0 + bcol];
        *(float4*)&Bs[brow][bcol] = bv;
        __syncthreads();

#pragma unroll
        for (int kk = 0; kk < 8; kk++) {
            float a[8], b[8];
            *(float4*)&a[0] = *(float4*)&As[kk][ty * 8];
            *(float4*)&a[4] = *(float4*)&As[kk][ty * 8 + 4];
            *(float4*)&b[0] = *(float4*)&Bs[kk][tx * 8];
            *(float4*)&b[4] = *(float4*)&Bs[kk][tx * 8 + 4];
#pragma unroll
            for (int i = 0; i < 8; i++)
#pragma unroll
                for (int j = 0; j < 8; j++) acc[i][j] += a[i] * b[j];
        }
        __syncthreads();
    }

#pragma unroll
    for (int i = 0; i < 8; i++) {
        int r = row0 + ty * 8 + i;
        if (r < M) {
#pragma unroll
            for (int j = 0; j < 8; j += 4) {
                int c = col0 + tx * 8 + j;
                float4 o;
                o.x = acc[i][j + 0] + bias[c + 0];
                o.y = acc[i][j + 1] + bias[c + 1];
                o.z = acc[i][j + 2] + bias[c + 2];
                o.w = acc[i][j + 3] + bias[c + 3];
                *(float4*)&C[(size_t)r * 512 + c] = o;
            }
        }
    }
}

// ---------------------------------------------------------------------------
// Gate dot products: gq[r] = q[r,:] . wg[0:512], gk[r] = k[r,:] . wg[512:1024]
// ---------------------------------------------------------------------------
__global__ __launch_bounds__(128) void gate_kernel(const float* __restrict__ wg)
{
    const int row = blockIdx.x;
    const int tid = threadIdx.x;
    float sq = 0.f, sk = 0.f;
#pragma unroll
    for (int e = tid; e < 512; e += 128) {
        sq += g_q[(size_t)row * 512 + e] * wg[e];
        sk += g_k[(size_t)row * 512 + e] * wg[512 + e];
    }
#pragma unroll
    for (int off = 16; off >= 1; off >>= 1) {
        sq += __shfl_down_sync(0xffffffffu, sq, off);
        sk += __shfl_down_sync(0xffffffffu, sk, off);
    }
    __shared__ float pq[4], pk[4];
    if ((tid & 31) == 0) { pq[tid >> 5] = sq; pk[tid >> 5] = sk; }
    __syncthreads();
    if (tid == 0) {
        g_gq[row] = pq[0] + pq[1] + pq[2] + pq[3];
        g_gk[row] = pk[0] + pk[1] + pk[2] + pk[3];
    }
}

// ---------------------------------------------------------------------------
// Banded flash attention with Gaussian bias + sigmoid pairwise gate.
// Q tile 64 rows, K tile 64 cols, D=64. 256 threads, 4x4 microtile.
// Shared layouts (stride 68 pad):
//   Qst[d][i], Kst[d][j] (aliased as Ss[i][j] after S compute), Vs[j][d]
// ---------------------------------------------------------------------------
#define STR 68

__global__ __launch_bounds__(256) void attn_kernel(const float* __restrict__ bg_ptr)
{
    extern __shared__ float smem[];
    float* Qst = smem;                 // 64*68
    float* Kst = Qst + 64 * STR;       // 64*68 (aliased as Ss)
    float* Vs  = Kst + 64 * STR;       // 64*68
    float* m_s = Vs + 64 * STR;        // 64
    float* l_s = m_s + 64;             // 64
    float* c_s = l_s + 64;             // 64
    float* gqs = c_s + 64;             // 64
    float* gks = gqs + 64;             // 64

    const int qb = blockIdx.x;         // 0..32
    const int h  = blockIdx.y;         // 0..7
    const int b  = blockIdx.z;         // 0..1
    const int q0 = qb * 64;
    const int tid = threadIdx.x;
    const int ty = tid >> 4, tx = tid & 15;
    const float bg = bg_ptr[0];

    // Load Q tile transposed: Qst[d][i]
#pragma unroll
    for (int it = 0; it < 16; it++) {
        int idx = it * 256 + tid;
        int i = idx >> 6, d = idx & 63;
        int gi = q0 + i;
        float v = 0.f;
        if (gi < SS) v = g_q[((size_t)(b * SS + gi)) * EE + h * 64 + d];
        Qst[d * STR + i] = v;
    }
    if (tid < 64) {
        int gi = q0 + tid;
        gqs[tid] = (gi < SS) ? g_gq[b * SS + gi] : 0.f;
        m_s[tid] = -1e30f;
        l_s[tid] = 0.f;
    }

    float acc[4][4];
#pragma unroll
    for (int i = 0; i < 4; i++)
#pragma unroll
        for (int j = 0; j < 4; j++) acc[i][j] = 0.f;

    int kstart = q0 - WINW; if (kstart < 0) kstart = 0;
    int kend = q0 + 64 + WINW; if (kend > SS) kend = SS;

    for (int k0 = kstart; k0 < kend; k0 += 64) {
        __syncthreads();  // protect Kst(=Ss)/Vs from previous iteration readers

        // Load K,V tiles
#pragma unroll
        for (int it = 0; it < 16; it++) {
            int idx = it * 256 + tid;
            int j = idx >> 6, d = idx & 63;
            int gj = k0 + j;
            float kv = 0.f, vv = 0.f;
            if (gj < SS) {
                size_t base = ((size_t)(b * SS + gj)) * EE + h * 64 + d;
                kv = g_k[base];
                vv = g_v[base];
            }
            Kst[d * STR + j] = kv;
            Vs[j * STR + d]  = vv;
        }
        if (tid < 64) {
            int gj = k0 + tid;
            gks[tid] = (gj < SS) ? g_gk[b * SS + gj] : 0.f;
        }
        __syncthreads();

        // S = Q @ K^T (4x4 per thread)
        float s[4][4];
#pragma unroll
        for (int i = 0; i < 4; i++)
#pragma unroll
            for (int j = 0; j < 4; j++) s[i][j] = 0.f;

#pragma unroll 8
        for (int d = 0; d < 64; d++) {
            float qa[4], kb[4];
            *(float4*)qa = *(float4*)&Qst[d * STR + ty * 4];
            *(float4*)kb = *(float4*)&Kst[d * STR + tx * 4];
#pragma unroll
            for (int i = 0; i < 4; i++)
#pragma unroll
                for (int j = 0; j < 4; j++) s[i][j] += qa[i] * kb[j];
        }

        // Epilogue: scale, Gaussian bias, sigmoid gate, band mask (in registers)
        float gqr[4], gkr[4];
#pragma unroll
        for (int i = 0; i < 4; i++) gqr[i] = gqs[ty * 4 + i];
#pragma unroll
        for (int j = 0; j < 4; j++) gkr[j] = gks[tx * 4 + j];

#pragma unroll
        for (int ii = 0; ii < 4; ii++) {
            int gi = q0 + ty * 4 + ii;
#pragma unroll
            for (int jj = 0; jj < 4; jj++) {
                int gj = k0 + tx * 4 + jj;
                int dd = gi - gj;
                float sv = -1e30f;
                if (gi < SS && gj < SS && dd <= WINW && dd >= -WINW) {
                    float z = gqr[ii] + gkr[jj] + bg;
                    float gate = __fdividef(1.f, 1.f + __expf(-z));
                    float d2 = (float)(dd * dd);
                    sv = (s[ii][jj] * SCALE + d2 * BIASC) * gate;
                }
                s[ii][jj] = sv;
            }
        }

        __syncthreads();  // all threads done reading Kst -> safe to alias as Ss
        float* Ss = Kst;
#pragma unroll
        for (int ii = 0; ii < 4; ii++)
            *(float4*)&Ss[(ty * 4 + ii) * STR + tx * 4] = *(float4*)&s[ii][0];
        __syncthreads();

        // Online softmax: 4 lanes per row (row = tid>>2, part = tid&3)
        {
            int row = tid >> 2, part = tid & 3;
            float mx = -1e30f;
#pragma unroll
            for (int c = 0; c < 16; c++)
                mx = fmaxf(mx, Ss[row * STR + part * 16 + c]);
            mx = fmaxf(mx, __shfl_xor_sync(0xffffffffu, mx, 1));
            mx = fmaxf(mx, __shfl_xor_sync(0xffffffffu, mx, 2));
            float mo = m_s[row];
            float mn = fmaxf(mo, mx);
            float sum = 0.f;
#pragma unroll
            for (int c = 0; c < 16; c++) {
                float sv = Ss[row * STR + part * 16 + c];
                float p = (sv <= -1e29f) ? 0.f : __expf(sv - mn);
                Ss[row * STR + part * 16 + c] = p;
                sum += p;
            }
            sum += __shfl_xor_sync(0xffffffffu, sum, 1);
            sum += __shfl_xor_sync(0xffffffffu, sum, 2);
            if (part == 0) {
                float c0 = __expf(mo - mn);
                m_s[row] = mn;
                l_s[row] = l_s[row] * c0 + sum;
                c_s[row] = c0;
            }
        }
        __syncthreads();

        // Rescale accumulator, then O += P @ V
        float cr[4];
#pragma unroll
        for (int i = 0; i < 4; i++) cr[i] = c_s[ty * 4 + i];
#pragma unroll
        for (int i = 0; i < 4; i++)
#pragma unroll
            for (int j = 0; j < 4; j++) acc[i][j] *= cr[i];

        float* Ss2 = Kst;
#pragma unroll 4
        for (int j = 0; j < 64; j++) {
            float vb[4];
            *(float4*)vb = *(float4*)&Vs[j * STR + tx * 4];
            float pa[4];
#pragma unroll
            for (int i = 0; i < 4; i++) pa[i] = Ss2[(ty * 4 + i) * STR + j];
#pragma unroll
            for (int i = 0; i < 4; i++)
#pragma unroll
                for (int d = 0; d < 4; d++) acc[i][d] += pa[i] * vb[d];
        }
    }

    // Final: divide by l, write to g_ao in [B,S,E] layout
#pragma unroll
    for (int ii = 0; ii < 4; ii++) {
        int gi = q0 + ty * 4 + ii;
        if (gi < SS) {
            float inv = 1.0f / l_s[ty * 4 + ii];
            float4 o;
            o.x = acc[ii][0] * inv;
            o.y = acc[ii][1] * inv;
            o.z = acc[ii][2] * inv;
            o.w = acc[ii][3] * inv;
            *(float4*)&g_ao[((size_t)(b * SS + gi)) * EE + h * 64 + tx * 4] = o;
        }
    }
}

// ---------------------------------------------------------------------------
extern "C" void kernel_launch(void* const* d_in, const int* in_sizes, int n_in,
                              void* d_out, int out_size)
{
    const float* x  = (const float*)d_in[0];
    const float* Wq = (const float*)d_in[1];
    const float* bq = (const float*)d_in[2];
    const float* Wk = (const float*)d_in[3];
    const float* bk = (const float*)d_in[4];
    const float* Wv = (const float*)d_in[5];
    const float* bv = (const float*)d_in[6];
    const float* Wo = (const float*)d_in[7];
    const float* bo = (const float*)d_in[8];
    const float* wg = (const float*)d_in[9];
    const float* bg = (const float*)d_in[10];
    float* out = (float*)d_out;

    float *pq, *pk, *pv, *pao;
    cudaGetSymbolAddress((void**)&pq, g_q);
    cudaGetSymbolAddress((void**)&pk, g_k);
    cudaGetSymbolAddress((void**)&pv, g_v);
    cudaGetSymbolAddress((void**)&pao, g_ao);

    const int smem_bytes = (3 * 64 * STR + 5 * 64) * (int)sizeof(float); // 53504
    cudaFuncSetAttribute(attn_kernel,
                         cudaFuncAttributeMaxDynamicSharedMemorySize, smem_bytes);

    dim3 ggemm(4, 33);  // N/128=4, ceil(4098/128)=33
    sgemm_bias_kernel<<<ggemm, 256>>>(x, Wq, bq, pq, MROWS);
    sgemm_bias_kernel<<<ggemm, 256>>>(x, Wk, bk, pk, MROWS);
    sgemm_bias_kernel<<<ggemm, 256>>>(x, Wv, bv, pv, MROWS);
    gate_kernel<<<MROWS, 128>>>(wg);
    attn_kernel<<<dim3(33, HH, BB), 256, smem_bytes>>>(bg);
    sgemm_bias_kernel<<<ggemm, 256>>>(pao, Wo, bo, out, MROWS);
}

// round 3
// speedup vs baseline: 1.8822x; 1.8822x over previous
#include <cuda_runtime.h>
#include <cstdint>
#include <math.h>

#define BB 2
#define SS 2049
#define EE 512
#define HH 8
#define WINW 1024
#define MROWS (BB * SS)                  // 4098
#define SCALE 0.125f                     // D^-0.5
#define BIASC (-1.9073486328125e-6f)     // -0.5/(512^2)
#define LOG2E 1.4426950408889634f

// Scratch (device globals: no allocation allowed)
__device__ float g_q[MROWS * EE];
__device__ float g_k[MROWS * EE];
__device__ float g_v[MROWS * EE];
__device__ float g_ao[MROWS * EE];
__device__ float g_gq[MROWS];
__device__ float g_gk[MROWS];

// ============================================================================
// helpers
// ============================================================================
__device__ __forceinline__ float tf32r(float x) {
    uint32_t u;
    asm("cvt.rna.tf32.f32 %0, %1;" : "=r"(u) : "f"(x));
    return __uint_as_float(u);
}
__device__ __forceinline__ void split2(float x, float& hi, float& lo) {
    hi = tf32r(x);
    lo = tf32r(x - hi);
}
__device__ __forceinline__ void mma_tf32(float* d, const uint32_t* a, const uint32_t* b) {
    asm volatile(
        "mma.sync.aligned.m16n8k8.row.col.f32.tf32.tf32.f32 "
        "{%0,%1,%2,%3}, {%4,%5,%6,%7}, {%8,%9}, {%0,%1,%2,%3};"
        : "+f"(d[0]), "+f"(d[1]), "+f"(d[2]), "+f"(d[3])
        : "r"(a[0]), "r"(a[1]), "r"(a[2]), "r"(a[3]), "r"(b[0]), "r"(b[1]));
}
__device__ __forceinline__ float rcpf(float x) {
    float r;
    asm("rcp.approx.f32 %0, %1;" : "=f"(r) : "f"(x));
    return r;
}
__device__ __forceinline__ float ex2f(float x) {
    float r;
    asm("ex2.approx.f32 %0, %1;" : "=f"(r) : "f"(x));
    return r;
}

// ---------------------------------------------------------------------------
// 3xTF32 GEMM: C[M,512] = A[M,512] @ B[512,512] + bias
// BM=128 BN=128 BK=16, 256 threads (8 warps: 4M x 2N), warp tile 32x64
// ---------------------------------------------------------------------------
#define GSTR 136
__global__ __launch_bounds__(256, 1) void gemm_tc_kernel(
    const float* __restrict__ A, const float* __restrict__ B,
    const float* __restrict__ bias, float* __restrict__ C, int M)
{
    __shared__ float Ah[16][GSTR], Al[16][GSTR];
    __shared__ float Bh[16][GSTR], Bl[16][GSTR];

    const int tid = threadIdx.x;
    const int wid = tid >> 5, lane = tid & 31;
    const int g = lane >> 2, tg = lane & 3;
    const int wm = wid >> 1, wn = wid & 1;
    const int row0 = blockIdx.y * 128, col0 = blockIdx.x * 128;
    const int wrow = wm * 32, wcol = wn * 64;

    float acc[2][8][4];
#pragma unroll
    for (int mt = 0; mt < 2; mt++)
#pragma unroll
        for (int nt = 0; nt < 8; nt++)
#pragma unroll
            for (int e = 0; e < 4; e++) acc[mt][nt][e] = 0.f;

    for (int k0 = 0; k0 < 512; k0 += 16) {
#pragma unroll
        for (int it = 0; it < 2; it++) {
            int idx = it * 256 + tid;
            {   // A: [128 rows][16 cols] -> Ah/Al[k][m]
                int r = idx >> 2, c4 = (idx & 3) * 4;
                float4 v = make_float4(0.f, 0.f, 0.f, 0.f);
                if (row0 + r < M)
                    v = *(const float4*)&A[(size_t)(row0 + r) * 512 + k0 + c4];
                float h, l;
                split2(v.x, h, l); Ah[c4 + 0][r] = h; Al[c4 + 0][r] = l;
                split2(v.y, h, l); Ah[c4 + 1][r] = h; Al[c4 + 1][r] = l;
                split2(v.z, h, l); Ah[c4 + 2][r] = h; Al[c4 + 2][r] = l;
                split2(v.w, h, l); Ah[c4 + 3][r] = h; Al[c4 + 3][r] = l;
            }
            {   // B: [16 k][128 n] -> Bh/Bl[k][n]
                int kr = idx >> 5, c32 = (idx & 31) * 4;
                float4 v = *(const float4*)&B[(size_t)(k0 + kr) * 512 + col0 + c32];
                float4 hv, lv;
                split2(v.x, hv.x, lv.x);
                split2(v.y, hv.y, lv.y);
                split2(v.z, hv.z, lv.z);
                split2(v.w, hv.w, lv.w);
                *(float4*)&Bh[kr][c32] = hv;
                *(float4*)&Bl[kr][c32] = lv;
            }
        }
        __syncthreads();

#pragma unroll
        for (int ks = 0; ks < 2; ks++) {
            const int kk = ks * 8;
            uint32_t ah[2][4], al[2][4];
#pragma unroll
            for (int mt = 0; mt < 2; mt++) {
                int r = wrow + mt * 16;
                ah[mt][0] = __float_as_uint(Ah[kk + tg][r + g]);
                ah[mt][1] = __float_as_uint(Ah[kk + tg][r + g + 8]);
                ah[mt][2] = __float_as_uint(Ah[kk + tg + 4][r + g]);
                ah[mt][3] = __float_as_uint(Ah[kk + tg + 4][r + g + 8]);
                al[mt][0] = __float_as_uint(Al[kk + tg][r + g]);
                al[mt][1] = __float_as_uint(Al[kk + tg][r + g + 8]);
                al[mt][2] = __float_as_uint(Al[kk + tg + 4][r + g]);
                al[mt][3] = __float_as_uint(Al[kk + tg + 4][r + g + 8]);
            }
            uint32_t bh[8][2], bl[8][2];
#pragma unroll
            for (int nt = 0; nt < 8; nt++) {
                int c = wcol + nt * 8;
                bh[nt][0] = __float_as_uint(Bh[kk + tg][c + g]);
                bh[nt][1] = __float_as_uint(Bh[kk + tg + 4][c + g]);
                bl[nt][0] = __float_as_uint(Bl[kk + tg][c + g]);
                bl[nt][1] = __float_as_uint(Bl[kk + tg + 4][c + g]);
            }
#pragma unroll
            for (int mt = 0; mt < 2; mt++)
#pragma unroll
                for (int nt = 0; nt < 8; nt++) {
                    mma_tf32(acc[mt][nt], al[mt], bh[nt]);
                    mma_tf32(acc[mt][nt], ah[mt], bl[nt]);
                    mma_tf32(acc[mt][nt], ah[mt], bh[nt]);
                }
        }
        __syncthreads();
    }

#pragma unroll
    for (int mt = 0; mt < 2; mt++) {
        int r0 = row0 + wrow + mt * 16 + g;
#pragma unroll
        for (int nt = 0; nt < 8; nt++) {
            int c = col0 + wcol + nt * 8 + 2 * tg;
            float b0v = bias[c], b1v = bias[c + 1];
            if (r0 < M) {
                float2 o = make_float2(acc[mt][nt][0] + b0v, acc[mt][nt][1] + b1v);
                *(float2*)&C[(size_t)r0 * 512 + c] = o;
            }
            if (r0 + 8 < M) {
                float2 o = make_float2(acc[mt][nt][2] + b0v, acc[mt][nt][3] + b1v);
                *(float2*)&C[(size_t)(r0 + 8) * 512 + c] = o;
            }
        }
    }
}

// ---------------------------------------------------------------------------
// Gate dot products
// ---------------------------------------------------------------------------
__global__ __launch_bounds__(128) void gate_kernel(const float* __restrict__ wg)
{
    const int row = blockIdx.x;
    const int tid = threadIdx.x;
    float sq = 0.f, sk = 0.f;
#pragma unroll
    for (int e = tid; e < 512; e += 128) {
        sq += g_q[(size_t)row * 512 + e] * wg[e];
        sk += g_k[(size_t)row * 512 + e] * wg[512 + e];
    }
#pragma unroll
    for (int off = 16; off >= 1; off >>= 1) {
        sq += __shfl_down_sync(0xffffffffu, sq, off);
        sk += __shfl_down_sync(0xffffffffu, sk, off);
    }
    __shared__ float pq[4], pk[4];
    if ((tid & 31) == 0) { pq[tid >> 5] = sq; pk[tid >> 5] = sk; }
    __syncthreads();
    if (tid == 0) {
        g_gq[row] = pq[0] + pq[1] + pq[2] + pq[3];
        g_gk[row] = pk[0] + pk[1] + pk[2] + pk[3];
    }
}

// ---------------------------------------------------------------------------
// TF32 mma.sync flash attention (no-max softmax: scores bounded ~[-3,2])
// Tq=64, Tk=64, D=64. 128 threads = 4 warps; warp owns 16 q-rows.
// ---------------------------------------------------------------------------
#define ASTR 68
#define ATTN_SMEM (4 * 64 * ASTR * 4 + 256)

__global__ __launch_bounds__(128, 2) void attn_mma_kernel(const float* __restrict__ bg_ptr)
{
    extern __shared__ char smem[];
    float (*Qs)[ASTR] = (float(*)[ASTR])(smem);
    float (*Ks)[ASTR] = (float(*)[ASTR])(smem + 64 * ASTR * 4);
    float (*Vs)[ASTR] = (float(*)[ASTR])(smem + 2 * 64 * ASTR * 4);
    float (*Ps)[ASTR] = (float(*)[ASTR])(smem + 3 * 64 * ASTR * 4);
    float* egk_s = (float*)(smem + 4 * 64 * ASTR * 4);   // 64 floats

    const int qb = blockIdx.x, h = blockIdx.y, b = blockIdx.z;
    const int q0 = qb * 64;
    const int tid = threadIdx.x;
    const int lane = tid & 31;
    const int g = lane >> 2, tg = lane & 3;
    const int wrow = (tid >> 5) * 16;
    const float bg = bg_ptr[0];

    const float* qp = g_q + ((size_t)(b * SS)) * EE + h * 64;
    const float* kp = g_k + ((size_t)(b * SS)) * EE + h * 64;
    const float* vp = g_v + ((size_t)(b * SS)) * EE + h * 64;

    // Stage Q (tf32)
#pragma unroll
    for (int it = 0; it < 8; it++) {
        int idx = it * 128 + tid;
        int r = idx >> 4, c4 = (idx & 15) * 4;
        int gi = q0 + r;
        float4 v = make_float4(0.f, 0.f, 0.f, 0.f);
        if (gi < SS) v = *(const float4*)(qp + (size_t)gi * EE + c4);
        Qs[r][c4 + 0] = tf32r(v.x);
        Qs[r][c4 + 1] = tf32r(v.y);
        Qs[r][c4 + 2] = tf32r(v.z);
        Qs[r][c4 + 3] = tf32r(v.w);
    }
    __syncthreads();

    // Hoist Q A-fragments into registers (reused for all k-tiles)
    uint32_t qa[8][4];
#pragma unroll
    for (int kk = 0; kk < 8; kk++) {
        qa[kk][0] = __float_as_uint(Qs[wrow + g][kk * 8 + tg]);
        qa[kk][1] = __float_as_uint(Qs[wrow + g + 8][kk * 8 + tg]);
        qa[kk][2] = __float_as_uint(Qs[wrow + g][kk * 8 + tg + 4]);
        qa[kk][3] = __float_as_uint(Qs[wrow + g + 8][kk * 8 + tg + 4]);
    }
    const int gi0 = q0 + wrow + g, gi1 = gi0 + 8;
    const float egq0 = __expf(-((gi0 < SS) ? g_gq[b * SS + gi0] : 0.f));
    const float egq1 = __expf(-((gi1 < SS) ? g_gq[b * SS + gi1] : 0.f));

    float oacc[8][4];
#pragma unroll
    for (int nt = 0; nt < 8; nt++)
#pragma unroll
        for (int e = 0; e < 4; e++) oacc[nt][e] = 0.f;
    float l0 = 0.f, l1 = 0.f;

    const float C1 = SCALE * LOG2E;
    const float C2 = BIASC * LOG2E;

    int kstart = q0 - WINW; if (kstart < 0) kstart = 0;
    int kend = q0 + 64 + WINW; if (kend > SS) kend = SS;

    for (int k0 = kstart; k0 < kend; k0 += 64) {
        __syncthreads();
        // Stage K, V (tf32) + exp(-gk - bg)
#pragma unroll
        for (int it = 0; it < 8; it++) {
            int idx = it * 128 + tid;
            int r = idx >> 4, c4 = (idx & 15) * 4;
            int gj = k0 + r;
            float4 kv = make_float4(0.f, 0.f, 0.f, 0.f);
            float4 vv = make_float4(0.f, 0.f, 0.f, 0.f);
            if (gj < SS) {
                kv = *(const float4*)(kp + (size_t)gj * EE + c4);
                vv = *(const float4*)(vp + (size_t)gj * EE + c4);
            }
            Ks[r][c4 + 0] = tf32r(kv.x);
            Ks[r][c4 + 1] = tf32r(kv.y);
            Ks[r][c4 + 2] = tf32r(kv.z);
            Ks[r][c4 + 3] = tf32r(kv.w);
            Vs[r][c4 + 0] = tf32r(vv.x);
            Vs[r][c4 + 1] = tf32r(vv.y);
            Vs[r][c4 + 2] = tf32r(vv.z);
            Vs[r][c4 + 3] = tf32r(vv.w);
        }
        if (tid < 64) {
            int gj = k0 + tid;
            float gk = (gj < SS) ? g_gk[b * SS + gj] : 0.f;
            egk_s[tid] = __expf(-gk - bg);
        }
        __syncthreads();

        // ---- S = Q @ K^T ----
        float sacc[8][4];
#pragma unroll
        for (int nt = 0; nt < 8; nt++)
#pragma unroll
            for (int e = 0; e < 4; e++) sacc[nt][e] = 0.f;
#pragma unroll
        for (int kk = 0; kk < 8; kk++) {
#pragma unroll
            for (int nt = 0; nt < 8; nt++) {
                uint32_t bf[2];
                bf[0] = __float_as_uint(Ks[nt * 8 + g][kk * 8 + tg]);
                bf[1] = __float_as_uint(Ks[nt * 8 + g][kk * 8 + tg + 4]);
                mma_tf32(sacc[nt], qa[kk], bf);
            }
        }

        // ---- Epilogue: gate + bias + mask + exp; P -> smem (tf32) ----
        float lt0 = 0.f, lt1 = 0.f;
#pragma unroll
        for (int nt = 0; nt < 8; nt++) {
            int lj = nt * 8 + 2 * tg;
            float2 eg = *(float2*)&egk_s[lj];
            int gj0 = k0 + lj, gj1 = gj0 + 1;

            int d00 = gi0 - gj0, d01 = gi0 - gj1, d10 = gi1 - gj0, d11 = gi1 - gj1;
            float p00, p01, p10, p11;
            {
                float gate = rcpf(fmaf(egq0, eg.x, 1.f));
                float p = ex2f((sacc[nt][0] * C1 + (float)(d00 * d00) * C2) * gate);
                p00 = (gj0 < SS && d00 <= WINW && d00 >= -WINW) ? tf32r(p) : 0.f;
            }
            {
                float gate = rcpf(fmaf(egq0, eg.y, 1.f));
                float p = ex2f((sacc[nt][1] * C1 + (float)(d01 * d01) * C2) * gate);
                p01 = (gj1 < SS && d01 <= WINW && d01 >= -WINW) ? tf32r(p) : 0.f;
            }
            {
                float gate = rcpf(fmaf(egq1, eg.x, 1.f));
                float p = ex2f((sacc[nt][2] * C1 + (float)(d10 * d10) * C2) * gate);
                p10 = (gj0 < SS && d10 <= WINW && d10 >= -WINW) ? tf32r(p) : 0.f;
            }
            {
                float gate = rcpf(fmaf(egq1, eg.y, 1.f));
                float p = ex2f((sacc[nt][3] * C1 + (float)(d11 * d11) * C2) * gate);
                p11 = (gj1 < SS && d11 <= WINW && d11 >= -WINW) ? tf32r(p) : 0.f;
            }
            lt0 += p00 + p01;
            lt1 += p10 + p11;
            *(float2*)&Ps[wrow + g][lj] = make_float2(p00, p01);
            *(float2*)&Ps[wrow + g + 8][lj] = make_float2(p10, p11);
        }
        lt0 += __shfl_xor_sync(0xffffffffu, lt0, 1);
        lt0 += __shfl_xor_sync(0xffffffffu, lt0, 2);
        lt1 += __shfl_xor_sync(0xffffffffu, lt1, 1);
        lt1 += __shfl_xor_sync(0xffffffffu, lt1, 2);
        l0 += lt0;
        l1 += lt1;
        __syncwarp();

        // ---- O += P @ V ----
#pragma unroll
        for (int kk = 0; kk < 8; kk++) {
            uint32_t pa[4];
            pa[0] = __float_as_uint(Ps[wrow + g][kk * 8 + tg]);
            pa[1] = __float_as_uint(Ps[wrow + g + 8][kk * 8 + tg]);
            pa[2] = __float_as_uint(Ps[wrow + g][kk * 8 + tg + 4]);
            pa[3] = __float_as_uint(Ps[wrow + g + 8][kk * 8 + tg + 4]);
#pragma unroll
            for (int nt = 0; nt < 8; nt++) {
                uint32_t bf[2];
                bf[0] = __float_as_uint(Vs[kk * 8 + tg][nt * 8 + g]);
                bf[1] = __float_as_uint(Vs[kk * 8 + tg + 4][nt * 8 + g]);
                mma_tf32(oacc[nt], pa, bf);
            }
        }
    }

    // ---- Final: O / l -> g_ao ----
    const float inv0 = rcpf(l0), inv1 = rcpf(l1);
    float* op = g_ao + ((size_t)(b * SS)) * EE + h * 64;
#pragma unroll
    for (int nt = 0; nt < 8; nt++) {
        int c = nt * 8 + 2 * tg;
        if (gi0 < SS)
            *(float2*)&op[(size_t)gi0 * EE + c] =
                make_float2(oacc[nt][0] * inv0, oacc[nt][1] * inv0);
        if (gi1 < SS)
            *(float2*)&op[(size_t)gi1 * EE + c] =
                make_float2(oacc[nt][2] * inv1, oacc[nt][3] * inv1);
    }
}

// ---------------------------------------------------------------------------
extern "C" void kernel_launch(void* const* d_in, const int* in_sizes, int n_in,
                              void* d_out, int out_size)
{
    const float* x  = (const float*)d_in[0];
    const float* Wq = (const float*)d_in[1];
    const float* bq = (const float*)d_in[2];
    const float* Wk = (const float*)d_in[3];
    const float* bk = (const float*)d_in[4];
    const float* Wv = (const float*)d_in[5];
    const float* bv = (const float*)d_in[6];
    const float* Wo = (const float*)d_in[7];
    const float* bo = (const float*)d_in[8];
    const float* wg = (const float*)d_in[9];
    const float* bg = (const float*)d_in[10];
    float* out = (float*)d_out;

    float *pq, *pk, *pv, *pao;
    cudaGetSymbolAddress((void**)&pq, g_q);
    cudaGetSymbolAddress((void**)&pk, g_k);
    cudaGetSymbolAddress((void**)&pv, g_v);
    cudaGetSymbolAddress((void**)&pao, g_ao);

    cudaFuncSetAttribute(attn_mma_kernel,
                         cudaFuncAttributeMaxDynamicSharedMemorySize, ATTN_SMEM);

    dim3 ggemm(4, 33);
    gemm_tc_kernel<<<ggemm, 256>>>(x, Wq, bq, pq, MROWS);
    gemm_tc_kernel<<<ggemm, 256>>>(x, Wk, bk, pk, MROWS);
    gemm_tc_kernel<<<ggemm, 256>>>(x, Wv, bv, pv, MROWS);
    gate_kernel<<<MROWS, 128>>>(wg);
    attn_mma_kernel<<<dim3(33, HH, BB), 128, ATTN_SMEM>>>(bg);
    gemm_tc_kernel<<<ggemm, 256>>>(pao, Wo, bo, out, MROWS);
}